// round 13
// baseline (speedup 1.0000x reference)
#include <cuda_runtime.h>
#include <cuda_bf16.h>
#include <cstdint>
#include <math.h>

#define BSZ 8
#define HN  512
#define LN  2048
#define D2N 32
#define CN  64          // chunk length
#define NC  (LN/CN)     // 32 chunks

// ---------------- scratch (device globals; no allocation allowed) ----------------
__device__ __align__(16) float  g_f [HN*LN];
__device__ __align__(16) float  g_k0[HN*LN];
__device__ float2               g_V [HN*CN*D2N];      // [h][m][d] = w^{C-1-m}
__device__ __align__(16) float  g_P [HN*2*D2N*CN];    // [h][dd][j]
__device__ float2               g_WC[HN*D2N];         // w^C
__device__ __align__(16) float  g_S [BSZ*HN*NC*2*D2N];
__device__ __align__(16) __nv_bfloat16 g_Wh[HN*HN], g_Wl[HN*HN];
__device__ __align__(16) __nv_bfloat16 g_gh[BSZ*HN*LN], g_gl[BSZ*HN*LN];

// ---------------- shared mma/ldsm helpers ----------------
__device__ __forceinline__ void ldsm_x4(uint32_t &r0, uint32_t &r1, uint32_t &r2, uint32_t &r3,
                                        uint32_t addr) {
    asm volatile("ldmatrix.sync.aligned.m8n8.x4.shared.b16 {%0,%1,%2,%3}, [%4];"
                 : "=r"(r0), "=r"(r1), "=r"(r2), "=r"(r3) : "r"(addr));
}
__device__ __forceinline__ void ldsm_x2t(uint32_t &r0, uint32_t &r1, uint32_t addr) {
    asm volatile("ldmatrix.sync.aligned.m8n8.x2.trans.shared.b16 {%0,%1}, [%2];"
                 : "=r"(r0), "=r"(r1) : "r"(addr));
}
__device__ __forceinline__ void mma_bf16(float* c, const uint32_t* a, const uint32_t* b) {
    asm volatile("mma.sync.aligned.m16n8k16.row.col.f32.bf16.bf16.f32 "
                 "{%0,%1,%2,%3},{%4,%5,%6,%7},{%8,%9},{%0,%1,%2,%3};"
                 : "+f"(c[0]), "+f"(c[1]), "+f"(c[2]), "+f"(c[3])
                 : "r"(a[0]), "r"(a[1]), "r"(a[2]), "r"(a[3]), "r"(b[0]), "r"(b[1]));
}

#define CP_ASYNC16(dst, src) asm volatile("cp.async.cg.shared.global [%0], [%1], 16;" :: "r"(dst), "l"(src))
#define CP_COMMIT()          asm volatile("cp.async.commit_group;" ::: "memory")
#define CP_WAIT1()           asm volatile("cp.async.wait_group 1;" ::: "memory")
#define CP_WAIT0()           asm volatile("cp.async.wait_group 0;" ::: "memory")

// ---------------- K1: f/k0 grid via phasor rotation ----------------
__global__ void __launch_bounds__(128) k_tables(const float* __restrict__ a,
                                                const float* __restrict__ th,
                                                const float* __restrict__ bb,
                                                const float* __restrict__ cc,
                                                const float* __restrict__ x0)
{
    int h = blockIdx.x;
    __shared__ float4 tab[D2N];
    __shared__ float s_aa[D2N], s_th[D2N];
    int tid = threadIdx.x;
    const float T = 1.0f / (float)(LN - 1);
    if (tid < D2N) {
        float aa = -fabsf(a[h*D2N + tid]);
        float t0 = th[h*D2N + tid];
        float q  = bb[h*D2N + tid] * cc[h*D2N + tid];
        float cx = cc[h*D2N + tid] * x0[h*D2N + tid];
        s_aa[tid] = aa; s_th[tid] = t0;
        float zs = 128.0f * T;
        float e = __expf(aa*zs);
        float si, co; __sincosf(t0*zs, &si, &co);
        tab[tid] = make_float4(e*co, e*si, q, cx);
    }
    __syncthreads();

    float z = T * (float)tid;
    float vr[D2N], vi[D2N];
    #pragma unroll
    for (int d = 0; d < D2N; d++) {
        float e = __expf(s_aa[d]*z);
        float si, co; __sincosf(s_th[d]*z, &si, &co);
        vr[d] = e*co; vi[d] = e*si;
    }
    for (int s = 0; s < 16; s++) {
        float fa = 0.f, ka = 0.f;
        #pragma unroll
        for (int d = 0; d < D2N; d++) {
            float4 t = tab[d];
            fa += t.z * vr[d];
            ka += t.w * vr[d];
            float nr = vr[d]*t.x - vi[d]*t.y;
            vi[d]    = vr[d]*t.y + vi[d]*t.x;
            vr[d] = nr;
        }
        g_f [h*LN + tid + 128*s] = 2.0f*T*fa;
        g_k0[h*LN + tid + 128*s] = 2.0f*ka;
    }
}

// ---------------- K1b: V/P/WC tables + W bf16 split, merged ----------------
__global__ void k_tables2(const float* __restrict__ a, const float* __restrict__ th,
                          const float* __restrict__ bb, const float* __restrict__ cc,
                          const float* __restrict__ W)
{
    int bid = blockIdx.x;
    if (bid >= 8192) {
        int i = (bid - 8192)*256 + threadIdx.x;
        float w = W[i];
        __nv_bfloat16 hi = __float2bfloat16(w);
        g_Wh[i] = hi;
        g_Wl[i] = __float2bfloat16(w - __bfloat162float(hi));
        return;
    }
    int t = bid*256 + threadIdx.x;
    int which = t >> 20;
    int r = t & 0xFFFFF;
    const float T = 1.0f / (float)(LN - 1);
    if (which == 0) {
        int d = r & 31, m = (r >> 5) & 63, h = r >> 11;
        float aa = -fabsf(a[h*D2N + d]);
        float t0 = th[h*D2N + d];
        float k = (float)(CN - 1 - m);
        float e = __expf(aa*T*k);
        float si, co; __sincosf(t0*T*k, &si, &co);
        g_V[(h*CN + m)*D2N + d] = make_float2(e*co, e*si);
        if (m == 0) {
            float kc = (float)CN;
            float ec = __expf(aa*T*kc);
            float s2, c2; __sincosf(t0*T*kc, &s2, &c2);
            g_WC[h*D2N + d] = make_float2(ec*c2, ec*s2);
        }
    } else {
        int j = r & 63, d = (r >> 6) & 31, h = r >> 11;
        float aa = -fabsf(a[h*D2N + d]);
        float t0 = th[h*D2N + d];
        float q  = bb[h*D2N + d] * cc[h*D2N + d];
        float k = (float)(j + 1);
        float e = __expf(aa*T*k);
        float si, co; __sincosf(t0*T*k, &si, &co);
        g_P[(h*2*D2N + d      )*CN + j] =  2.0f*T*q*e*co;
        g_P[(h*2*D2N + D2N + d)*CN + j] = -2.0f*T*q*e*si;
    }
}

// ---------------- K2: chunk states, register-resident A + 2-level scan ----------------
__global__ void __launch_bounds__(128) k_chunkA(const float* __restrict__ u)
{
    int row = blockIdx.x;
    int h = row & (HN-1);
    __shared__ float  u_s[LN];
    __shared__ float2 V_s[CN*D2N];
    __shared__ float2 Tex[4][D2N];
    __shared__ float2 Off[4][D2N];
    int tid = threadIdx.x;
    for (int i = tid; i < LN/4; i += 128)
        ((float4*)u_s)[i] = ((const float4*)(u + row*LN))[i];
    const float4* Vg4 = (const float4*)(g_V + h*CN*D2N);
    for (int i = tid; i < CN*D2N/2; i += 128)
        ((float4*)V_s)[i] = Vg4[i];
    __syncthreads();

    int d = tid & 31;
    int w = tid >> 5;
    float ar[8] = {}, ai[8] = {};
    #pragma unroll 2
    for (int m4 = 0; m4 < CN; m4 += 4) {
        float4 uv[8];
        #pragma unroll
        for (int c = 0; c < 8; c++)
            uv[c] = *(const float4*)&u_s[(8*w + c)*CN + m4];
        #pragma unroll
        for (int mm = 0; mm < 4; mm++) {
            float2 v = V_s[(m4+mm)*D2N + d];
            #pragma unroll
            for (int c = 0; c < 8; c++) {
                float um = ((const float*)&uv[c])[mm];
                ar[c] += v.x * um;
                ai[c] += v.y * um;
            }
        }
    }

    float2 wc = g_WC[h*D2N + d];
    float Sr[8], Si[8];
    {
        float sr = 0.f, si = 0.f;
        #pragma unroll
        for (int c = 0; c < 8; c++) {
            Sr[c] = sr; Si[c] = si;
            float nsr = wc.x*sr - wc.y*si + ar[c];
            si        = wc.x*si + wc.y*sr + ai[c];
            sr = nsr;
        }
        Tex[w][d] = make_float2(sr, si);
    }
    __syncthreads();

    if (w == 0) {
        float2 w2 = make_float2(wc.x*wc.x - wc.y*wc.y, 2.f*wc.x*wc.y);
        float2 w4 = make_float2(w2.x*w2.x - w2.y*w2.y, 2.f*w2.x*w2.y);
        float2 w8 = make_float2(w4.x*w4.x - w4.y*w4.y, 2.f*w4.x*w4.y);
        float orr = 0.f, oi = 0.f;
        #pragma unroll
        for (int ww = 0; ww < 4; ww++) {
            Off[ww][d] = make_float2(orr, oi);
            float2 t = Tex[ww][d];
            float no = w8.x*orr - w8.y*oi + t.x;
            oi       = w8.x*oi + w8.y*orr + t.y;
            orr = no;
        }
    }
    __syncthreads();

    float2 off = Off[w][d];
    float cr = off.x, ci = off.y;
    #pragma unroll
    for (int c = 0; c < 8; c++) {
        int idx = (row*NC + 8*w + c)*2*D2N;
        g_S[idx + d]       = cr + Sr[c];
        g_S[idx + D2N + d] = ci + Si[c];
        float ncr = wc.x*cr - wc.y*ci;
        ci        = wc.x*ci + wc.y*cr;
        cr = ncr;
    }
}

// ---------------- K4: scalar conv + cross term, warp-uniform balanced strips ----------------
// 8 warps; lane = chunk c (0..31). Warp w processes jj-strips {w, 15-w} sequentially:
// every warp does exactly 17 m4-blocks -> no divergence, balanced load.
__global__ void __launch_bounds__(256) k_main(const float* __restrict__ u,
                                              const float* __restrict__ Din)
{
    int row = blockIdx.x;
    int h = row & (HN-1);
    __shared__ float ut[CN*33];                 // u transposed [m][c], pad 33
    __shared__ __align__(16) float fbuf[4+CN];  // 4-zero guard + f[0..63]
    __shared__ __align__(16) float P_s[2*D2N*CN];   // [dd][j]; later reused for e_t
    __shared__ float S_s[NC*65];                // [c][dd] pad 65; later out staging
    int tid = threadIdx.x;

    for (int i = tid; i < LN; i += 256) {
        float v = u[row*LN + i];
        ut[(i & 63)*33 + (i >> 6)] = v;
    }
    const float4* Pg = (const float4*)(g_P + h*2*D2N*CN);
    for (int i = tid; i < (2*D2N*CN)/4; i += 256) ((float4*)P_s)[i] = Pg[i];
    if (tid < 4)  fbuf[tid] = 0.f;
    if (tid < CN) fbuf[4+tid] = g_f[h*LN + tid];
    for (int i = tid; i < NC*2*D2N; i += 256)
        S_s[(i >> 6)*65 + (i & 63)] = g_S[row*NC*2*D2N + i];
    __syncthreads();

    int warp = tid >> 5;
    int c    = tid & 31;          // lane = chunk
    float y[2][4];

    #pragma unroll
    for (int sidx = 0; sidx < 2; sidx++) {
        int strip = (sidx == 0) ? warp : (15 - warp);
        int jj4 = strip * 4;
        float* ys = y[sidx];
        ys[0] = 0.f; ys[1] = 0.f; ys[2] = 0.f; ys[3] = 0.f;

        // triangular conv, rolling 8-reg f window, uniform nb = strip+1
        float w[8];
        *(float4*)&w[4] = *(const float4*)&fbuf[4 + jj4];
        *(float4*)&w[0] = *(const float4*)&fbuf[jj4];          // guard zeros at strip 0
        int nb = strip + 1;
        for (int b = 0; b < nb; b++) {
            int mb = 4*b;
            #pragma unroll
            for (int mm = 0; mm < 4; mm++) {
                float ua = ut[(mb+mm)*33 + c];   // stride-33 gather, conflict-free
                ys[0] += ua*w[4-mm]; ys[1] += ua*w[5-mm];
                ys[2] += ua*w[6-mm]; ys[3] += ua*w[7-mm];
            }
            w[4] = w[0]; w[5] = w[1]; w[6] = w[2]; w[7] = w[3];
            if (b + 1 < nb)
                *(float4*)&w[0] = *(const float4*)&fbuf[jj4 - 4*(b+1)];
            else
                { w[0]=0.f; w[1]=0.f; w[2]=0.f; w[3]=0.f; }
        }

        // cross-chunk term: y += P[dd][jj] * S[c][dd]
        #pragma unroll 4
        for (int dd = 0; dd < 2*D2N; dd++) {
            float4 p = *(const float4*)&P_s[dd*CN + jj4];   // warp-uniform broadcast
            float s = S_s[c*65 + dd];                        // stride-65, conflict-free
            ys[0] += p.x*s; ys[1] += p.y*s; ys[2] += p.z*s; ys[3] += p.w*s;
        }
    }

    // stage combined epilogue term e[l] = k0[l] - 0.5*u0*f[l] transposed (reuse P_s)
    float u0f   = ut[0];
    float coefU = Din[h] - 0.5f * fbuf[4];
    __syncthreads();
    for (int i = tid; i < LN; i += 256) {
        float e = g_k0[h*LN + i] - 0.5f*u0f*g_f[h*LN + i];
        P_s[(i & 63)*33 + (i >> 6)] = e;
    }
    __syncthreads();

    // epilogue + GELU -> stage into S_s [c][j] (S no longer needed)
    #pragma unroll
    for (int sidx = 0; sidx < 2; sidx++) {
        int strip = (sidx == 0) ? warp : (15 - warp);
        int jj4 = strip * 4;
        #pragma unroll
        for (int r = 0; r < 4; r++) {
            int jr = jj4 + r;
            float uv = ut[jr*33 + c];
            float yv = y[sidx][r] + P_s[jr*33 + c] + coefU*uv;
            float g = 0.5f * yv * (1.0f + erff(yv * 0.70710678118654752f));
            S_s[c*65 + jr] = g;
        }
    }
    __syncthreads();
    for (int i = tid; i < LN; i += 256) {
        float v = S_s[(i >> 6)*65 + (i & 63)];
        __nv_bfloat16 hi = __float2bfloat16(v);
        g_gh[row*LN + i] = hi;
        g_gl[row*LN + i] = __float2bfloat16(v - __bfloat162float(hi));
    }
}

// ---------------- K5: tensor-core GEMM, bf16 split, cp.async double-buffered ----------------
#define ASTR 40    // bf16 elems per A smem row (80B)
#define BSTR 136   // bf16 elems per B smem row (272B)
#define A_ST (128*ASTR)
#define B_ST (32*BSTR)

__device__ __forceinline__ void gemm_prefetch(int tid,
    const __nv_bfloat16* Wh_t, const __nv_bfloat16* Wl_t,
    const __nv_bfloat16* Gh_t, const __nv_bfloat16* Gl_t,
    __nv_bfloat16* ah, __nv_bfloat16* al,
    __nv_bfloat16* bh, __nv_bfloat16* bl, int k0)
{
    #pragma unroll
    for (int rpt = 0; rpt < 2; rpt++) {
        int idx = tid + rpt*256;
        int arow = idx >> 2, acol = (idx & 3) * 8;
        uint32_t da = (uint32_t)__cvta_generic_to_shared(ah + arow*ASTR + acol);
        CP_ASYNC16(da, Wh_t + (size_t)arow*HN + k0 + acol);
        da = (uint32_t)__cvta_generic_to_shared(al + arow*ASTR + acol);
        CP_ASYNC16(da, Wl_t + (size_t)arow*HN + k0 + acol);
        int brow = idx >> 4, bcol = (idx & 15) * 8;
        uint32_t db = (uint32_t)__cvta_generic_to_shared(bh + brow*BSTR + bcol);
        CP_ASYNC16(db, Gh_t + (size_t)(k0 + brow)*LN + bcol);
        db = (uint32_t)__cvta_generic_to_shared(bl + brow*BSTR + bcol);
        CP_ASYNC16(db, Gl_t + (size_t)(k0 + brow)*LN + bcol);
    }
}

__global__ void __launch_bounds__(256) k_gemm_tc(const float* __restrict__ bias,
                                                 float* __restrict__ out)
{
    extern __shared__ __align__(16) __nv_bfloat16 smp[];
    __nv_bfloat16* pAH[2] = { smp,              smp + A_ST };
    __nv_bfloat16* pAL[2] = { smp + 2*A_ST,     smp + 3*A_ST };
    __nv_bfloat16* pBH[2] = { smp + 4*A_ST,          smp + 4*A_ST + B_ST };
    __nv_bfloat16* pBL[2] = { smp + 4*A_ST + 2*B_ST, smp + 4*A_ST + 3*B_ST };

    int bz = blockIdx.z, bm = blockIdx.y, bn = blockIdx.x;
    int tid  = threadIdx.x;
    int warp = tid >> 5, lane = tid & 31;
    int wm = (warp >> 2) * 64;
    int wn = (warp & 3) * 32;

    const __nv_bfloat16* Wh_t = g_Wh + (size_t)(bm*128)*HN;
    const __nv_bfloat16* Wl_t = g_Wl + (size_t)(bm*128)*HN;
    const __nv_bfloat16* Gh_t = g_gh + (size_t)bz*HN*LN + bn*128;
    const __nv_bfloat16* Gl_t = g_gl + (size_t)bz*HN*LN + bn*128;

    float acc[4][4][4];
    #pragma unroll
    for (int i = 0; i < 4; i++)
        #pragma unroll
        for (int j = 0; j < 4; j++)
            #pragma unroll
            for (int q = 0; q < 4; q++) acc[i][j][q] = 0.f;

    gemm_prefetch(tid, Wh_t, Wl_t, Gh_t, Gl_t, pAH[0], pAL[0], pBH[0], pBL[0], 0);
    CP_COMMIT();

    for (int s = 0; s < 16; s++) {
        int cur = s & 1;
        if (s < 15) {
            gemm_prefetch(tid, Wh_t, Wl_t, Gh_t, Gl_t,
                          pAH[cur^1], pAL[cur^1], pBH[cur^1], pBL[cur^1], (s+1)*32);
            CP_COMMIT();
            CP_WAIT1();
        } else {
            CP_WAIT0();
        }
        __syncthreads();

        uint32_t ah_u = (uint32_t)__cvta_generic_to_shared(pAH[cur]);
        uint32_t al_u = (uint32_t)__cvta_generic_to_shared(pAL[cur]);
        uint32_t bh_u = (uint32_t)__cvta_generic_to_shared(pBH[cur]);
        uint32_t bl_u = (uint32_t)__cvta_generic_to_shared(pBL[cur]);

        #pragma unroll
        for (int kk = 0; kk < 32; kk += 16) {
            uint32_t ah[4][4], al[4][4], bh[4][2], bl[4][2];
            int arow = wm + (lane & 7) + ((lane >> 3) & 1) * 8;
            int acol = kk + (lane >> 4) * 8;
            #pragma unroll
            for (int mi = 0; mi < 4; mi++) {
                uint32_t ad = ah_u + (uint32_t)(((arow + mi*16)*ASTR + acol) * 2);
                ldsm_x4(ah[mi][0], ah[mi][1], ah[mi][2], ah[mi][3], ad);
                ad = al_u + (uint32_t)(((arow + mi*16)*ASTR + acol) * 2);
                ldsm_x4(al[mi][0], al[mi][1], al[mi][2], al[mi][3], ad);
            }
            int brow = kk + (lane & 15);
            #pragma unroll
            for (int ni = 0; ni < 4; ni++) {
                uint32_t bd = bh_u + (uint32_t)((brow*BSTR + wn + ni*8) * 2);
                ldsm_x2t(bh[ni][0], bh[ni][1], bd);
                bd = bl_u + (uint32_t)((brow*BSTR + wn + ni*8) * 2);
                ldsm_x2t(bl[ni][0], bl[ni][1], bd);
            }
            #pragma unroll
            for (int mi = 0; mi < 4; mi++)
                #pragma unroll
                for (int ni = 0; ni < 4; ni++) {
                    mma_bf16(acc[mi][ni], ah[mi], bh[ni]);
                    mma_bf16(acc[mi][ni], ah[mi], bl[ni]);
                    mma_bf16(acc[mi][ni], al[mi], bh[ni]);
                }
        }
        __syncthreads();
    }

    #pragma unroll
    for (int mi = 0; mi < 4; mi++) {
        int m = bm*128 + wm + mi*16 + (lane >> 2);
        float bi0 = bias[m], bi8 = bias[m + 8];
        #pragma unroll
        for (int ni = 0; ni < 4; ni++) {
            int n = bn*128 + wn + ni*8 + (lane & 3)*2;
            float2 v0 = make_float2(acc[mi][ni][0] + bi0, acc[mi][ni][1] + bi0);
            float2 v1 = make_float2(acc[mi][ni][2] + bi8, acc[mi][ni][3] + bi8);
            *(float2*)(out + (size_t)(bz*HN + m)*LN + n)     = v0;
            *(float2*)(out + (size_t)(bz*HN + m + 8)*LN + n) = v1;
        }
    }
}

// ---------------- launch ----------------
extern "C" void kernel_launch(void* const* d_in, const int* in_sizes, int n_in,
                              void* d_out, int out_size)
{
    const float* u     = (const float*)d_in[0];
    const float* a     = (const float*)d_in[1];
    const float* theta = (const float*)d_in[2];
    const float* bcoef = (const float*)d_in[3];
    const float* ccoef = (const float*)d_in[4];
    const float* x0    = (const float*)d_in[5];
    const float* Dv    = (const float*)d_in[6];
    const float* W     = (const float*)d_in[7];
    const float* bias  = (const float*)d_in[8];
    float* out = (float*)d_out;

    const int gemm_smem = (4*A_ST + 4*B_ST) * 2;   // 75776 bytes
    static int configured = 0;
    if (!configured) {
        cudaFuncSetAttribute(k_gemm_tc, cudaFuncAttributeMaxDynamicSharedMemorySize, gemm_smem);
        configured = 1;
    }

    k_tables <<<HN, 128>>>(a, theta, bcoef, ccoef, x0);
    k_tables2<<<8192 + HN*HN/256, 256>>>(a, theta, bcoef, ccoef, W);
    k_chunkA <<<BSZ*HN, 128>>>(u);
    k_main   <<<BSZ*HN, 256>>>(u, Dv);
    k_gemm_tc<<<dim3(LN/128, HN/128, BSZ), 256, gemm_smem>>>(bias, out);
}

// round 15
// speedup vs baseline: 1.0472x; 1.0472x over previous
#include <cuda_runtime.h>
#include <cuda_bf16.h>
#include <cstdint>
#include <math.h>

#define BSZ 8
#define HN  512
#define LN  2048
#define D2N 32
#define CN  64          // chunk length
#define NC  (LN/CN)     // 32 chunks

// ---------------- scratch (device globals; no allocation allowed) ----------------
__device__ __align__(16) float  g_f [HN*LN];
__device__ __align__(16) float  g_k0[HN*LN];
__device__ float2               g_V [HN*CN*D2N];      // [h][m][d] = w^{C-1-m}
__device__ __align__(16) float  g_P [HN*2*D2N*CN];    // [h][dd][j]
__device__ float2               g_WC[HN*D2N];         // w^C
__device__ __align__(16) float  g_S [BSZ*HN*NC*2*D2N];
__device__ __align__(16) __nv_bfloat16 g_Wh[HN*HN], g_Wl[HN*HN];
__device__ __align__(16) __nv_bfloat16 g_gh[BSZ*HN*LN], g_gl[BSZ*HN*LN];

// ---------------- shared mma/ldsm helpers ----------------
__device__ __forceinline__ void ldsm_x4(uint32_t &r0, uint32_t &r1, uint32_t &r2, uint32_t &r3,
                                        uint32_t addr) {
    asm volatile("ldmatrix.sync.aligned.m8n8.x4.shared.b16 {%0,%1,%2,%3}, [%4];"
                 : "=r"(r0), "=r"(r1), "=r"(r2), "=r"(r3) : "r"(addr));
}
__device__ __forceinline__ void ldsm_x2t(uint32_t &r0, uint32_t &r1, uint32_t addr) {
    asm volatile("ldmatrix.sync.aligned.m8n8.x2.trans.shared.b16 {%0,%1}, [%2];"
                 : "=r"(r0), "=r"(r1) : "r"(addr));
}
__device__ __forceinline__ void mma_bf16(float* c, const uint32_t* a, const uint32_t* b) {
    asm volatile("mma.sync.aligned.m16n8k16.row.col.f32.bf16.bf16.f32 "
                 "{%0,%1,%2,%3},{%4,%5,%6,%7},{%8,%9},{%0,%1,%2,%3};"
                 : "+f"(c[0]), "+f"(c[1]), "+f"(c[2]), "+f"(c[3])
                 : "r"(a[0]), "r"(a[1]), "r"(a[2]), "r"(a[3]), "r"(b[0]), "r"(b[1]));
}

#define CP_ASYNC16(dst, src) asm volatile("cp.async.cg.shared.global [%0], [%1], 16;" :: "r"(dst), "l"(src))
#define CP_COMMIT()          asm volatile("cp.async.commit_group;" ::: "memory")
#define CP_WAIT1()           asm volatile("cp.async.wait_group 1;" ::: "memory")
#define CP_WAIT0()           asm volatile("cp.async.wait_group 0;" ::: "memory")

// ---------------- K1: f/k0 grid via phasor rotation ----------------
__global__ void __launch_bounds__(128) k_tables(const float* __restrict__ a,
                                                const float* __restrict__ th,
                                                const float* __restrict__ bb,
                                                const float* __restrict__ cc,
                                                const float* __restrict__ x0)
{
    int h = blockIdx.x;
    __shared__ float4 tab[D2N];
    __shared__ float s_aa[D2N], s_th[D2N];
    int tid = threadIdx.x;
    const float T = 1.0f / (float)(LN - 1);
    if (tid < D2N) {
        float aa = -fabsf(a[h*D2N + tid]);
        float t0 = th[h*D2N + tid];
        float q  = bb[h*D2N + tid] * cc[h*D2N + tid];
        float cx = cc[h*D2N + tid] * x0[h*D2N + tid];
        s_aa[tid] = aa; s_th[tid] = t0;
        float zs = 128.0f * T;
        float e = __expf(aa*zs);
        float si, co; __sincosf(t0*zs, &si, &co);
        tab[tid] = make_float4(e*co, e*si, q, cx);
    }
    __syncthreads();

    float z = T * (float)tid;
    float vr[D2N], vi[D2N];
    #pragma unroll
    for (int d = 0; d < D2N; d++) {
        float e = __expf(s_aa[d]*z);
        float si, co; __sincosf(s_th[d]*z, &si, &co);
        vr[d] = e*co; vi[d] = e*si;
    }
    for (int s = 0; s < 16; s++) {
        float fa = 0.f, ka = 0.f;
        #pragma unroll
        for (int d = 0; d < D2N; d++) {
            float4 t = tab[d];
            fa += t.z * vr[d];
            ka += t.w * vr[d];
            float nr = vr[d]*t.x - vi[d]*t.y;
            vi[d]    = vr[d]*t.y + vi[d]*t.x;
            vr[d] = nr;
        }
        g_f [h*LN + tid + 128*s] = 2.0f*T*fa;
        g_k0[h*LN + tid + 128*s] = 2.0f*ka;
    }
}

// ---------------- K1b: V/P/WC tables + W bf16 split, merged ----------------
__global__ void k_tables2(const float* __restrict__ a, const float* __restrict__ th,
                          const float* __restrict__ bb, const float* __restrict__ cc,
                          const float* __restrict__ W)
{
    int bid = blockIdx.x;
    if (bid >= 8192) {
        int i = (bid - 8192)*256 + threadIdx.x;
        float w = W[i];
        __nv_bfloat16 hi = __float2bfloat16(w);
        g_Wh[i] = hi;
        g_Wl[i] = __float2bfloat16(w - __bfloat162float(hi));
        return;
    }
    int t = bid*256 + threadIdx.x;
    int which = t >> 20;
    int r = t & 0xFFFFF;
    const float T = 1.0f / (float)(LN - 1);
    if (which == 0) {
        int d = r & 31, m = (r >> 5) & 63, h = r >> 11;
        float aa = -fabsf(a[h*D2N + d]);
        float t0 = th[h*D2N + d];
        float k = (float)(CN - 1 - m);
        float e = __expf(aa*T*k);
        float si, co; __sincosf(t0*T*k, &si, &co);
        g_V[(h*CN + m)*D2N + d] = make_float2(e*co, e*si);
        if (m == 0) {
            float kc = (float)CN;
            float ec = __expf(aa*T*kc);
            float s2, c2; __sincosf(t0*T*kc, &s2, &c2);
            g_WC[h*D2N + d] = make_float2(ec*c2, ec*s2);
        }
    } else {
        int j = r & 63, d = (r >> 6) & 31, h = r >> 11;
        float aa = -fabsf(a[h*D2N + d]);
        float t0 = th[h*D2N + d];
        float q  = bb[h*D2N + d] * cc[h*D2N + d];
        float k = (float)(j + 1);
        float e = __expf(aa*T*k);
        float si, co; __sincosf(t0*T*k, &si, &co);
        g_P[(h*2*D2N + d      )*CN + j] =  2.0f*T*q*e*co;
        g_P[(h*2*D2N + D2N + d)*CN + j] = -2.0f*T*q*e*si;
    }
}

// ---------------- K2: chunk states, register-resident A + in-place 2-level scan ----------------
__global__ void __launch_bounds__(128) k_chunkA(const float* __restrict__ u)
{
    int row = blockIdx.x;
    int h = row & (HN-1);
    __shared__ float  u_s[LN];
    __shared__ float2 V_s[CN*D2N];
    __shared__ float2 Tex[4][D2N];
    __shared__ float2 Off[4][D2N];
    int tid = threadIdx.x;
    for (int i = tid; i < LN/4; i += 128)
        ((float4*)u_s)[i] = ((const float4*)(u + row*LN))[i];
    const float4* Vg4 = (const float4*)(g_V + h*CN*D2N);
    for (int i = tid; i < CN*D2N/2; i += 128)
        ((float4*)V_s)[i] = Vg4[i];
    __syncthreads();

    int d = tid & 31;
    int w = tid >> 5;              // warp w owns chunks 8w..8w+7
    float ar[8] = {}, ai[8] = {};
    #pragma unroll 2
    for (int m4 = 0; m4 < CN; m4 += 4) {
        // V for this m4 block in registers, uv one chunk at a time
        float2 v0 = V_s[(m4+0)*D2N + d];
        float2 v1 = V_s[(m4+1)*D2N + d];
        float2 v2 = V_s[(m4+2)*D2N + d];
        float2 v3 = V_s[(m4+3)*D2N + d];
        #pragma unroll
        for (int c = 0; c < 8; c++) {
            float4 uv = *(const float4*)&u_s[(8*w + c)*CN + m4];   // warp-broadcast
            ar[c] += v0.x*uv.x; ai[c] += v0.y*uv.x;
            ar[c] += v1.x*uv.y; ai[c] += v1.y*uv.y;
            ar[c] += v2.x*uv.z; ai[c] += v2.y*uv.z;
            ar[c] += v3.x*uv.w; ai[c] += v3.y*uv.w;
        }
    }

    // in-place local scan: ar/ai become the state ENTERING each local chunk
    float2 wc = g_WC[h*D2N + d];
    {
        float pr = 0.f, pi = 0.f;
        #pragma unroll
        for (int c = 0; c < 8; c++) {
            float tr = ar[c], ti = ai[c];
            ar[c] = pr; ai[c] = pi;
            float npr = wc.x*pr - wc.y*pi + tr;
            pi        = wc.x*pi + wc.y*pr + ti;
            pr = npr;
        }
        Tex[w][d] = make_float2(pr, pi);   // warp total
    }
    __syncthreads();

    // warp 0: combine 4 warp totals with wc^8
    if (w == 0) {
        float2 w2 = make_float2(wc.x*wc.x - wc.y*wc.y, 2.f*wc.x*wc.y);
        float2 w4 = make_float2(w2.x*w2.x - w2.y*w2.y, 2.f*w2.x*w2.y);
        float w8x = w4.x*w4.x - w4.y*w4.y;
        float w8y = 2.f*w4.x*w4.y;
        float orr = 0.f, oi = 0.f;
        #pragma unroll
        for (int ww = 0; ww < 4; ww++) {
            Off[ww][d] = make_float2(orr, oi);
            float2 t = Tex[ww][d];
            float no = w8x*orr - w8y*oi + t.x;
            oi       = w8x*oi + w8y*orr + t.y;
            orr = no;
        }
    }
    __syncthreads();

    // apply offset: state entering chunk 8w+c = wc^c * off + local_enter[c]
    float2 off = Off[w][d];
    float cr = off.x, ci = off.y;
    #pragma unroll
    for (int c = 0; c < 8; c++) {
        int idx = (row*NC + 8*w + c)*2*D2N;
        g_S[idx + d]       = cr + ar[c];
        g_S[idx + D2N + d] = ci + ai[c];
        float ncr = wc.x*cr - wc.y*ci;
        ci        = wc.x*ci + wc.y*cr;
        cr = ncr;
    }
}

// ---------------- K4: intra-chunk conv + cross term + GELU + bf16 split (r10 version) ----------------
__global__ void __launch_bounds__(256) k_main(const float* __restrict__ u,
                                              const float* __restrict__ Din)
{
    int row = blockIdx.x;
    int h = row & (HN-1);
    __shared__ float ut[CN*33];
    __shared__ __align__(16) float fbuf[4+CN];  // 4-zero guard + f[0..63]
    __shared__ __align__(16) float P_s[2*D2N*CN];
    __shared__ float S_s[NC*65];
    int tid = threadIdx.x;

    for (int i = tid; i < LN; i += 256) {
        float v = u[row*LN + i];
        ut[(i & 63)*33 + (i >> 6)] = v;
    }
    const float4* Pg = (const float4*)(g_P + h*2*D2N*CN);
    for (int i = tid; i < (2*D2N*CN)/4; i += 256) ((float4*)P_s)[i] = Pg[i];
    if (tid < 4)  fbuf[tid] = 0.f;
    if (tid < CN) fbuf[4+tid] = g_f[h*LN + tid];
    for (int i = tid; i < NC*2*D2N; i += 256)
        S_s[(i >> 6)*65 + (i & 63)] = g_S[row*NC*2*D2N + i];
    __syncthreads();

    int cp  = tid & 15;
    int jjg = tid >> 4;
    int jj4 = jjg * 4;
    int c0 = cp, c1 = cp + 16;
    float u0f   = ut[0];
    float coefU = Din[h] - 0.5f * fbuf[4];

    float y0[4] = {0.f,0.f,0.f,0.f}, y1[4] = {0.f,0.f,0.f,0.f};

    float w[8];
    *(float4*)&w[4] = *(const float4*)&fbuf[4 + jj4];
    *(float4*)&w[0] = *(const float4*)&fbuf[jj4];
    int nb = jjg + 1;
    for (int b = 0; b < nb; b++) {
        int mb = 4*b;
        #pragma unroll
        for (int mm = 0; mm < 4; mm++) {
            float ua = ut[(mb+mm)*33 + c0];
            float ub = ut[(mb+mm)*33 + c1];
            y0[0] += ua*w[4-mm]; y0[1] += ua*w[5-mm]; y0[2] += ua*w[6-mm]; y0[3] += ua*w[7-mm];
            y1[0] += ub*w[4-mm]; y1[1] += ub*w[5-mm]; y1[2] += ub*w[6-mm]; y1[3] += ub*w[7-mm];
        }
        w[4] = w[0]; w[5] = w[1]; w[6] = w[2]; w[7] = w[3];
        if (b + 1 < nb)
            *(float4*)&w[0] = *(const float4*)&fbuf[jj4 - 4*(b+1)];
        else
            { w[0]=0.f; w[1]=0.f; w[2]=0.f; w[3]=0.f; }
    }

    #pragma unroll 4
    for (int dd = 0; dd < 2*D2N; dd++) {
        float4 p = *(const float4*)&P_s[dd*CN + jj4];
        float sa = S_s[c0*65 + dd];
        float sb = S_s[c1*65 + dd];
        y0[0] += p.x*sa; y0[1] += p.y*sa; y0[2] += p.z*sa; y0[3] += p.w*sa;
        y1[0] += p.x*sb; y1[1] += p.y*sb; y1[2] += p.z*sb; y1[3] += p.w*sb;
    }

    __syncthreads();
    for (int i = tid; i < LN; i += 256) {
        float e = g_k0[h*LN + i] - 0.5f*u0f*g_f[h*LN + i];
        P_s[(i & 63)*33 + (i >> 6)] = e;
    }
    __syncthreads();

    #pragma unroll
    for (int r = 0; r < 4; r++) {
        int jr = jj4 + r;
        float uv0 = ut[jr*33 + c0];
        float uv1 = ut[jr*33 + c1];
        float ya = y0[r] + P_s[jr*33 + c0] + coefU*uv0;
        float yb = y1[r] + P_s[jr*33 + c1] + coefU*uv1;
        float ga = 0.5f * ya * (1.0f + erff(ya * 0.70710678118654752f));
        float gb = 0.5f * yb * (1.0f + erff(yb * 0.70710678118654752f));
        S_s[c0*65 + jr] = ga;
        S_s[c1*65 + jr] = gb;
    }
    __syncthreads();
    for (int i = tid; i < LN; i += 256) {
        float v = S_s[(i >> 6)*65 + (i & 63)];
        __nv_bfloat16 hi = __float2bfloat16(v);
        g_gh[row*LN + i] = hi;
        g_gl[row*LN + i] = __float2bfloat16(v - __bfloat162float(hi));
    }
}

// ---------------- K5: tensor-core GEMM, bf16 split, cp.async double-buffered ----------------
#define ASTR 40    // bf16 elems per A smem row (80B)
#define BSTR 136   // bf16 elems per B smem row (272B)
#define A_ST (128*ASTR)
#define B_ST (32*BSTR)

__device__ __forceinline__ void gemm_prefetch(int tid,
    const __nv_bfloat16* Wh_t, const __nv_bfloat16* Wl_t,
    const __nv_bfloat16* Gh_t, const __nv_bfloat16* Gl_t,
    __nv_bfloat16* ah, __nv_bfloat16* al,
    __nv_bfloat16* bh, __nv_bfloat16* bl, int k0)
{
    #pragma unroll
    for (int rpt = 0; rpt < 2; rpt++) {
        int idx = tid + rpt*256;
        int arow = idx >> 2, acol = (idx & 3) * 8;
        uint32_t da = (uint32_t)__cvta_generic_to_shared(ah + arow*ASTR + acol);
        CP_ASYNC16(da, Wh_t + (size_t)arow*HN + k0 + acol);
        da = (uint32_t)__cvta_generic_to_shared(al + arow*ASTR + acol);
        CP_ASYNC16(da, Wl_t + (size_t)arow*HN + k0 + acol);
        int brow = idx >> 4, bcol = (idx & 15) * 8;
        uint32_t db = (uint32_t)__cvta_generic_to_shared(bh + brow*BSTR + bcol);
        CP_ASYNC16(db, Gh_t + (size_t)(k0 + brow)*LN + bcol);
        db = (uint32_t)__cvta_generic_to_shared(bl + brow*BSTR + bcol);
        CP_ASYNC16(db, Gl_t + (size_t)(k0 + brow)*LN + bcol);
    }
}

__global__ void __launch_bounds__(256) k_gemm_tc(const float* __restrict__ bias,
                                                 float* __restrict__ out)
{
    extern __shared__ __align__(16) __nv_bfloat16 smp[];
    __nv_bfloat16* pAH[2] = { smp,              smp + A_ST };
    __nv_bfloat16* pAL[2] = { smp + 2*A_ST,     smp + 3*A_ST };
    __nv_bfloat16* pBH[2] = { smp + 4*A_ST,          smp + 4*A_ST + B_ST };
    __nv_bfloat16* pBL[2] = { smp + 4*A_ST + 2*B_ST, smp + 4*A_ST + 3*B_ST };

    int bz = blockIdx.z, bm = blockIdx.y, bn = blockIdx.x;
    int tid  = threadIdx.x;
    int warp = tid >> 5, lane = tid & 31;
    int wm = (warp >> 2) * 64;
    int wn = (warp & 3) * 32;

    const __nv_bfloat16* Wh_t = g_Wh + (size_t)(bm*128)*HN;
    const __nv_bfloat16* Wl_t = g_Wl + (size_t)(bm*128)*HN;
    const __nv_bfloat16* Gh_t = g_gh + (size_t)bz*HN*LN + bn*128;
    const __nv_bfloat16* Gl_t = g_gl + (size_t)bz*HN*LN + bn*128;

    float acc[4][4][4];
    #pragma unroll
    for (int i = 0; i < 4; i++)
        #pragma unroll
        for (int j = 0; j < 4; j++)
            #pragma unroll
            for (int q = 0; q < 4; q++) acc[i][j][q] = 0.f;

    gemm_prefetch(tid, Wh_t, Wl_t, Gh_t, Gl_t, pAH[0], pAL[0], pBH[0], pBL[0], 0);
    CP_COMMIT();

    for (int s = 0; s < 16; s++) {
        int cur = s & 1;
        if (s < 15) {
            gemm_prefetch(tid, Wh_t, Wl_t, Gh_t, Gl_t,
                          pAH[cur^1], pAL[cur^1], pBH[cur^1], pBL[cur^1], (s+1)*32);
            CP_COMMIT();
            CP_WAIT1();
        } else {
            CP_WAIT0();
        }
        __syncthreads();

        uint32_t ah_u = (uint32_t)__cvta_generic_to_shared(pAH[cur]);
        uint32_t al_u = (uint32_t)__cvta_generic_to_shared(pAL[cur]);
        uint32_t bh_u = (uint32_t)__cvta_generic_to_shared(pBH[cur]);
        uint32_t bl_u = (uint32_t)__cvta_generic_to_shared(pBL[cur]);

        #pragma unroll
        for (int kk = 0; kk < 32; kk += 16) {
            uint32_t ah[4][4], al[4][4], bh[4][2], bl[4][2];
            int arow = wm + (lane & 7) + ((lane >> 3) & 1) * 8;
            int acol = kk + (lane >> 4) * 8;
            #pragma unroll
            for (int mi = 0; mi < 4; mi++) {
                uint32_t ad = ah_u + (uint32_t)(((arow + mi*16)*ASTR + acol) * 2);
                ldsm_x4(ah[mi][0], ah[mi][1], ah[mi][2], ah[mi][3], ad);
                ad = al_u + (uint32_t)(((arow + mi*16)*ASTR + acol) * 2);
                ldsm_x4(al[mi][0], al[mi][1], al[mi][2], al[mi][3], ad);
            }
            int brow = kk + (lane & 15);
            #pragma unroll
            for (int ni = 0; ni < 4; ni++) {
                uint32_t bd = bh_u + (uint32_t)((brow*BSTR + wn + ni*8) * 2);
                ldsm_x2t(bh[ni][0], bh[ni][1], bd);
                bd = bl_u + (uint32_t)((brow*BSTR + wn + ni*8) * 2);
                ldsm_x2t(bl[ni][0], bl[ni][1], bd);
            }
            #pragma unroll
            for (int mi = 0; mi < 4; mi++)
                #pragma unroll
                for (int ni = 0; ni < 4; ni++) {
                    mma_bf16(acc[mi][ni], ah[mi], bh[ni]);
                    mma_bf16(acc[mi][ni], ah[mi], bl[ni]);
                    mma_bf16(acc[mi][ni], al[mi], bh[ni]);
                }
        }
        __syncthreads();
    }

    #pragma unroll
    for (int mi = 0; mi < 4; mi++) {
        int m = bm*128 + wm + mi*16 + (lane >> 2);
        float bi0 = bias[m], bi8 = bias[m + 8];
        #pragma unroll
        for (int ni = 0; ni < 4; ni++) {
            int n = bn*128 + wn + ni*8 + (lane & 3)*2;
            float2 v0 = make_float2(acc[mi][ni][0] + bi0, acc[mi][ni][1] + bi0);
            float2 v1 = make_float2(acc[mi][ni][2] + bi8, acc[mi][ni][3] + bi8);
            *(float2*)(out + (size_t)(bz*HN + m)*LN + n)     = v0;
            *(float2*)(out + (size_t)(bz*HN + m + 8)*LN + n) = v1;
        }
    }
}

// ---------------- launch ----------------
extern "C" void kernel_launch(void* const* d_in, const int* in_sizes, int n_in,
                              void* d_out, int out_size)
{
    const float* u     = (const float*)d_in[0];
    const float* a     = (const float*)d_in[1];
    const float* theta = (const float*)d_in[2];
    const float* bcoef = (const float*)d_in[3];
    const float* ccoef = (const float*)d_in[4];
    const float* x0    = (const float*)d_in[5];
    const float* Dv    = (const float*)d_in[6];
    const float* W     = (const float*)d_in[7];
    const float* bias  = (const float*)d_in[8];
    float* out = (float*)d_out;

    const int gemm_smem = (4*A_ST + 4*B_ST) * 2;   // 75776 bytes
    static cudaStream_t s2 = nullptr;
    static cudaEvent_t evFork = nullptr, evJoin = nullptr;
    if (!s2) {   // one-time setup on the (non-captured) correctness call
        cudaFuncSetAttribute(k_gemm_tc, cudaFuncAttributeMaxDynamicSharedMemorySize, gemm_smem);
        cudaStreamCreateWithFlags(&s2, cudaStreamNonBlocking);
        cudaEventCreateWithFlags(&evFork, cudaEventDisableTiming);
        cudaEventCreateWithFlags(&evJoin, cudaEventDisableTiming);
    }

    // fork: k_tables (f/k0, needed only by k_main) runs concurrently with
    // the tables2 -> chunkA chain on the main stream.
    cudaEventRecord(evFork, 0);
    cudaStreamWaitEvent(s2, evFork, 0);
    k_tables <<<HN, 128, 0, s2>>>(a, theta, bcoef, ccoef, x0);
    cudaEventRecord(evJoin, s2);

    k_tables2<<<8192 + HN*HN/256, 256>>>(a, theta, bcoef, ccoef, W);
    k_chunkA <<<BSZ*HN, 128>>>(u);

    cudaStreamWaitEvent(0, evJoin, 0);   // join before k_main consumes g_f/g_k0
    k_main   <<<BSZ*HN, 256>>>(u, Dv);
    k_gemm_tc<<<dim3(LN/128, HN/128, BSZ), 256, gemm_smem>>>(bias, out);
}

// round 16
// speedup vs baseline: 1.0914x; 1.0422x over previous
#include <cuda_runtime.h>
#include <cuda_bf16.h>
#include <cstdint>
#include <math.h>

#define BSZ 8
#define HN  512
#define LN  2048
#define D2N 32
#define CN  64          // chunk length
#define NC  (LN/CN)     // 32 chunks

// ---------------- scratch (device globals; no allocation allowed) ----------------
__device__ __align__(16) float  g_f [HN*LN];
__device__ __align__(16) float  g_k0[HN*LN];
__device__ float2               g_V [HN*CN*D2N];      // [h][m][d] = w^{C-1-m}
__device__ __align__(16) float  g_P [HN*2*D2N*CN];    // [h][dd][j]
__device__ float2               g_WC[HN*D2N];         // w^C
__device__ __align__(16) __nv_bfloat16 g_Wh[HN*HN], g_Wl[HN*HN];
__device__ __align__(16) __nv_bfloat16 g_gh[BSZ*HN*LN], g_gl[BSZ*HN*LN];

// ---------------- shared mma/ldsm helpers ----------------
__device__ __forceinline__ void ldsm_x4(uint32_t &r0, uint32_t &r1, uint32_t &r2, uint32_t &r3,
                                        uint32_t addr) {
    asm volatile("ldmatrix.sync.aligned.m8n8.x4.shared.b16 {%0,%1,%2,%3}, [%4];"
                 : "=r"(r0), "=r"(r1), "=r"(r2), "=r"(r3) : "r"(addr));
}
__device__ __forceinline__ void ldsm_x2t(uint32_t &r0, uint32_t &r1, uint32_t addr) {
    asm volatile("ldmatrix.sync.aligned.m8n8.x2.trans.shared.b16 {%0,%1}, [%2];"
                 : "=r"(r0), "=r"(r1) : "r"(addr));
}
__device__ __forceinline__ void mma_bf16(float* c, const uint32_t* a, const uint32_t* b) {
    asm volatile("mma.sync.aligned.m16n8k16.row.col.f32.bf16.bf16.f32 "
                 "{%0,%1,%2,%3},{%4,%5,%6,%7},{%8,%9},{%0,%1,%2,%3};"
                 : "+f"(c[0]), "+f"(c[1]), "+f"(c[2]), "+f"(c[3])
                 : "r"(a[0]), "r"(a[1]), "r"(a[2]), "r"(a[3]), "r"(b[0]), "r"(b[1]));
}

#define CP_ASYNC16(dst, src) asm volatile("cp.async.cg.shared.global [%0], [%1], 16;" :: "r"(dst), "l"(src))
#define CP_COMMIT()          asm volatile("cp.async.commit_group;" ::: "memory")
#define CP_WAIT1()           asm volatile("cp.async.wait_group 1;" ::: "memory")
#define CP_WAIT0()           asm volatile("cp.async.wait_group 0;" ::: "memory")

// ---------------- K1: f/k0 grid via phasor rotation ----------------
__global__ void __launch_bounds__(128) k_tables(const float* __restrict__ a,
                                                const float* __restrict__ th,
                                                const float* __restrict__ bb,
                                                const float* __restrict__ cc,
                                                const float* __restrict__ x0)
{
    int h = blockIdx.x;
    __shared__ float4 tab[D2N];
    __shared__ float s_aa[D2N], s_th[D2N];
    int tid = threadIdx.x;
    const float T = 1.0f / (float)(LN - 1);
    if (tid < D2N) {
        float aa = -fabsf(a[h*D2N + tid]);
        float t0 = th[h*D2N + tid];
        float q  = bb[h*D2N + tid] * cc[h*D2N + tid];
        float cx = cc[h*D2N + tid] * x0[h*D2N + tid];
        s_aa[tid] = aa; s_th[tid] = t0;
        float zs = 128.0f * T;
        float e = __expf(aa*zs);
        float si, co; __sincosf(t0*zs, &si, &co);
        tab[tid] = make_float4(e*co, e*si, q, cx);
    }
    __syncthreads();

    float z = T * (float)tid;
    float vr[D2N], vi[D2N];
    #pragma unroll
    for (int d = 0; d < D2N; d++) {
        float e = __expf(s_aa[d]*z);
        float si, co; __sincosf(s_th[d]*z, &si, &co);
        vr[d] = e*co; vi[d] = e*si;
    }
    for (int s = 0; s < 16; s++) {
        float fa = 0.f, ka = 0.f;
        #pragma unroll
        for (int d = 0; d < D2N; d++) {
            float4 t = tab[d];
            fa += t.z * vr[d];
            ka += t.w * vr[d];
            float nr = vr[d]*t.x - vi[d]*t.y;
            vi[d]    = vr[d]*t.y + vi[d]*t.x;
            vr[d] = nr;
        }
        g_f [h*LN + tid + 128*s] = 2.0f*T*fa;
        g_k0[h*LN + tid + 128*s] = 2.0f*ka;
    }
}

// ---------------- K1b: V/P/WC tables + W bf16 split, merged ----------------
__global__ void k_tables2(const float* __restrict__ a, const float* __restrict__ th,
                          const float* __restrict__ bb, const float* __restrict__ cc,
                          const float* __restrict__ W)
{
    int bid = blockIdx.x;
    if (bid >= 8192) {
        int i = (bid - 8192)*256 + threadIdx.x;
        float w = W[i];
        __nv_bfloat16 hi = __float2bfloat16(w);
        g_Wh[i] = hi;
        g_Wl[i] = __float2bfloat16(w - __bfloat162float(hi));
        return;
    }
    int t = bid*256 + threadIdx.x;
    int which = t >> 20;
    int r = t & 0xFFFFF;
    const float T = 1.0f / (float)(LN - 1);
    if (which == 0) {
        int d = r & 31, m = (r >> 5) & 63, h = r >> 11;
        float aa = -fabsf(a[h*D2N + d]);
        float t0 = th[h*D2N + d];
        float k = (float)(CN - 1 - m);
        float e = __expf(aa*T*k);
        float si, co; __sincosf(t0*T*k, &si, &co);
        g_V[(h*CN + m)*D2N + d] = make_float2(e*co, e*si);
        if (m == 0) {
            float kc = (float)CN;
            float ec = __expf(aa*T*kc);
            float s2, c2; __sincosf(t0*T*kc, &s2, &c2);
            g_WC[h*D2N + d] = make_float2(ec*c2, ec*s2);
        }
    } else {
        int j = r & 63, d = (r >> 6) & 31, h = r >> 11;
        float aa = -fabsf(a[h*D2N + d]);
        float t0 = th[h*D2N + d];
        float q  = bb[h*D2N + d] * cc[h*D2N + d];
        float k = (float)(j + 1);
        float e = __expf(aa*T*k);
        float si, co; __sincosf(t0*T*k, &si, &co);
        g_P[(h*2*D2N + d      )*CN + j] =  2.0f*T*q*e*co;
        g_P[(h*2*D2N + D2N + d)*CN + j] = -2.0f*T*q*e*si;
    }
}

// ---------------- K4: fused chunk-states + scan + conv + cross + GELU + bf16 split ----------------
__global__ void __launch_bounds__(256) k_main(const float* __restrict__ u,
                                              const float* __restrict__ Din)
{
    int row = blockIdx.x;
    int h = row & (HN-1);
    __shared__ float ut[CN*33];                 // u transposed [m][c], pad 33
    __shared__ __align__(16) float fbuf[4+CN];  // 4-zero guard + f[0..63]
    __shared__ __align__(16) float VP[2*D2N*CN];// V (phase A) then P (phase B); e_t later
    __shared__ float S_s[NC*65];                // S states, then out staging
    __shared__ float2 Tex[8][D2N];
    __shared__ float2 Off[8][D2N];
    int tid = threadIdx.x;

    const float* urow = u + (size_t)row*LN;
    for (int i = tid; i < LN; i += 256) {
        float v = urow[i];
        ut[(i & 63)*33 + (i >> 6)] = v;
    }
    {
        const float4* Vg4 = (const float4*)(g_V + (size_t)h*CN*D2N);
        #pragma unroll
        for (int r = 0; r < 4; r++)
            ((float4*)VP)[tid + r*256] = Vg4[tid + r*256];
    }
    if (tid < 4)  fbuf[tid] = 0.f;
    if (tid < CN) fbuf[4+tid] = g_f[h*LN + tid];
    __syncthreads();

    // ---- phase A: per-chunk partial states (warp w owns chunks 4w..4w+3, lane=d) ----
    int d = tid & 31;
    int w = tid >> 5;
    const float2* V_s = (const float2*)VP;
    float ar[4] = {}, ai[4] = {};
    #pragma unroll 2
    for (int m4 = 0; m4 < CN; m4 += 4) {
        float2 v0 = V_s[(m4+0)*D2N + d];
        float2 v1 = V_s[(m4+1)*D2N + d];
        float2 v2 = V_s[(m4+2)*D2N + d];
        float2 v3 = V_s[(m4+3)*D2N + d];
        #pragma unroll
        for (int c = 0; c < 4; c++) {
            float4 uv = *(const float4*)&urow[(4*w + c)*CN + m4];  // L1-hot broadcast
            ar[c] += v0.x*uv.x; ai[c] += v0.y*uv.x;
            ar[c] += v1.x*uv.y; ai[c] += v1.y*uv.y;
            ar[c] += v2.x*uv.z; ai[c] += v2.y*uv.z;
            ar[c] += v3.x*uv.w; ai[c] += v3.y*uv.w;
        }
    }
    // in-place local scan (enter-states) + warp total
    float2 wc = g_WC[h*D2N + d];
    {
        float pr = 0.f, pi = 0.f;
        #pragma unroll
        for (int c = 0; c < 4; c++) {
            float tr = ar[c], ti = ai[c];
            ar[c] = pr; ai[c] = pi;
            float npr = wc.x*pr - wc.y*pi + tr;
            pi        = wc.x*pi + wc.y*pr + ti;
            pr = npr;
        }
        Tex[w][d] = make_float2(pr, pi);
    }
    __syncthreads();
    if (w == 0) {        // combine 8 warp totals with wc^4
        float2 w2 = make_float2(wc.x*wc.x - wc.y*wc.y, 2.f*wc.x*wc.y);
        float w4x = w2.x*w2.x - w2.y*w2.y;
        float w4y = 2.f*w2.x*w2.y;
        float orr = 0.f, oi = 0.f;
        #pragma unroll
        for (int ww = 0; ww < 8; ww++) {
            Off[ww][d] = make_float2(orr, oi);
            float2 t = Tex[ww][d];
            float no = w4x*orr - w4y*oi + t.x;
            oi       = w4x*oi + w4y*orr + t.y;
            orr = no;
        }
    }
    __syncthreads();
    {   // apply offsets; write S directly to smem
        float2 off = Off[w][d];
        float cr = off.x, ci = off.y;
        #pragma unroll
        for (int c = 0; c < 4; c++) {
            int cc = 4*w + c;
            S_s[cc*65 + d]       = cr + ar[c];
            S_s[cc*65 + D2N + d] = ci + ai[c];
            float ncr = wc.x*cr - wc.y*ci;
            ci        = wc.x*ci + wc.y*cr;
            cr = ncr;
        }
    }
    __syncthreads();

    // ---- prefetch P over VP (V dead), overlapped with conv ----
    {
        const float* Pg = g_P + (size_t)h*2*D2N*CN;
        uint32_t base = (uint32_t)__cvta_generic_to_shared(VP);
        #pragma unroll
        for (int r = 0; r < 4; r++) {
            int idx = tid + r*256;
            CP_ASYNC16(base + idx*16, Pg + idx*4);
        }
        CP_COMMIT();
    }

    // ---- phase B: triangular conv (ut + fbuf only) ----
    int cp  = tid & 15;
    int jjg = tid >> 4;
    int jj4 = jjg * 4;
    int c0 = cp, c1 = cp + 16;
    float u0f   = ut[0];
    float coefU = Din[h] - 0.5f * fbuf[4];

    float y0[4] = {0.f,0.f,0.f,0.f}, y1[4] = {0.f,0.f,0.f,0.f};

    float wv[8];
    *(float4*)&wv[4] = *(const float4*)&fbuf[4 + jj4];
    *(float4*)&wv[0] = *(const float4*)&fbuf[jj4];
    int nb = jjg + 1;
    for (int b = 0; b < nb; b++) {
        int mb = 4*b;
        #pragma unroll
        for (int mm = 0; mm < 4; mm++) {
            float ua = ut[(mb+mm)*33 + c0];
            float ub = ut[(mb+mm)*33 + c1];
            y0[0] += ua*wv[4-mm]; y0[1] += ua*wv[5-mm]; y0[2] += ua*wv[6-mm]; y0[3] += ua*wv[7-mm];
            y1[0] += ub*wv[4-mm]; y1[1] += ub*wv[5-mm]; y1[2] += ub*wv[6-mm]; y1[3] += ub*wv[7-mm];
        }
        wv[4] = wv[0]; wv[5] = wv[1]; wv[6] = wv[2]; wv[7] = wv[3];
        if (b + 1 < nb)
            *(float4*)&wv[0] = *(const float4*)&fbuf[jj4 - 4*(b+1)];
        else
            { wv[0]=0.f; wv[1]=0.f; wv[2]=0.f; wv[3]=0.f; }
    }

    // ---- cross-chunk term (needs P in VP) ----
    CP_WAIT0();
    __syncthreads();
    const float* P_s = VP;
    #pragma unroll 4
    for (int dd = 0; dd < 2*D2N; dd++) {
        float4 p = *(const float4*)&P_s[dd*CN + jj4];
        float sa = S_s[c0*65 + dd];
        float sb = S_s[c1*65 + dd];
        y0[0] += p.x*sa; y0[1] += p.y*sa; y0[2] += p.z*sa; y0[3] += p.w*sa;
        y1[0] += p.x*sb; y1[1] += p.y*sb; y1[2] += p.z*sb; y1[3] += p.w*sb;
    }

    // ---- e-staging: e[l] = k0[l] - 0.5*u0*f[l], transposed into VP ----
    __syncthreads();
    float* e_t = (float*)VP;
    for (int i = tid; i < LN; i += 256) {
        float e = g_k0[h*LN + i] - 0.5f*u0f*g_f[h*LN + i];
        e_t[(i & 63)*33 + (i >> 6)] = e;
    }
    __syncthreads();

    // ---- epilogue + GELU -> stage into S_s (S dead) ----
    #pragma unroll
    for (int r = 0; r < 4; r++) {
        int jr = jj4 + r;
        float uv0 = ut[jr*33 + c0];
        float uv1 = ut[jr*33 + c1];
        float ya = y0[r] + e_t[jr*33 + c0] + coefU*uv0;
        float yb = y1[r] + e_t[jr*33 + c1] + coefU*uv1;
        float ga = 0.5f * ya * (1.0f + erff(ya * 0.70710678118654752f));
        float gb = 0.5f * yb * (1.0f + erff(yb * 0.70710678118654752f));
        S_s[c0*65 + jr] = ga;
        S_s[c1*65 + jr] = gb;
    }
    __syncthreads();
    for (int i = tid; i < LN; i += 256) {
        float v = S_s[(i >> 6)*65 + (i & 63)];
        __nv_bfloat16 hi = __float2bfloat16(v);
        g_gh[(size_t)row*LN + i] = hi;
        g_gl[(size_t)row*LN + i] = __float2bfloat16(v - __bfloat162float(hi));
    }
}

// ---------------- K5: tensor-core GEMM, bf16 split, cp.async double-buffered ----------------
#define ASTR 40    // bf16 elems per A smem row (80B)
#define BSTR 136   // bf16 elems per B smem row (272B)
#define A_ST (128*ASTR)
#define B_ST (32*BSTR)

__device__ __forceinline__ void gemm_prefetch(int tid,
    const __nv_bfloat16* Wh_t, const __nv_bfloat16* Wl_t,
    const __nv_bfloat16* Gh_t, const __nv_bfloat16* Gl_t,
    __nv_bfloat16* ah, __nv_bfloat16* al,
    __nv_bfloat16* bh, __nv_bfloat16* bl, int k0)
{
    #pragma unroll
    for (int rpt = 0; rpt < 2; rpt++) {
        int idx = tid + rpt*256;
        int arow = idx >> 2, acol = (idx & 3) * 8;
        uint32_t da = (uint32_t)__cvta_generic_to_shared(ah + arow*ASTR + acol);
        CP_ASYNC16(da, Wh_t + (size_t)arow*HN + k0 + acol);
        da = (uint32_t)__cvta_generic_to_shared(al + arow*ASTR + acol);
        CP_ASYNC16(da, Wl_t + (size_t)arow*HN + k0 + acol);
        int brow = idx >> 4, bcol = (idx & 15) * 8;
        uint32_t db = (uint32_t)__cvta_generic_to_shared(bh + brow*BSTR + bcol);
        CP_ASYNC16(db, Gh_t + (size_t)(k0 + brow)*LN + bcol);
        db = (uint32_t)__cvta_generic_to_shared(bl + brow*BSTR + bcol);
        CP_ASYNC16(db, Gl_t + (size_t)(k0 + brow)*LN + bcol);
    }
}

__global__ void __launch_bounds__(256) k_gemm_tc(const float* __restrict__ bias,
                                                 float* __restrict__ out)
{
    extern __shared__ __align__(16) __nv_bfloat16 smp[];
    __nv_bfloat16* pAH[2] = { smp,              smp + A_ST };
    __nv_bfloat16* pAL[2] = { smp + 2*A_ST,     smp + 3*A_ST };
    __nv_bfloat16* pBH[2] = { smp + 4*A_ST,          smp + 4*A_ST + B_ST };
    __nv_bfloat16* pBL[2] = { smp + 4*A_ST + 2*B_ST, smp + 4*A_ST + 3*B_ST };

    int bz = blockIdx.z, bm = blockIdx.y, bn = blockIdx.x;
    int tid  = threadIdx.x;
    int warp = tid >> 5, lane = tid & 31;
    int wm = (warp >> 2) * 64;
    int wn = (warp & 3) * 32;

    const __nv_bfloat16* Wh_t = g_Wh + (size_t)(bm*128)*HN;
    const __nv_bfloat16* Wl_t = g_Wl + (size_t)(bm*128)*HN;
    const __nv_bfloat16* Gh_t = g_gh + (size_t)bz*HN*LN + bn*128;
    const __nv_bfloat16* Gl_t = g_gl + (size_t)bz*HN*LN + bn*128;

    float acc[4][4][4];
    #pragma unroll
    for (int i = 0; i < 4; i++)
        #pragma unroll
        for (int j = 0; j < 4; j++)
            #pragma unroll
            for (int q = 0; q < 4; q++) acc[i][j][q] = 0.f;

    gemm_prefetch(tid, Wh_t, Wl_t, Gh_t, Gl_t, pAH[0], pAL[0], pBH[0], pBL[0], 0);
    CP_COMMIT();

    for (int s = 0; s < 16; s++) {
        int cur = s & 1;
        if (s < 15) {
            gemm_prefetch(tid, Wh_t, Wl_t, Gh_t, Gl_t,
                          pAH[cur^1], pAL[cur^1], pBH[cur^1], pBL[cur^1], (s+1)*32);
            CP_COMMIT();
            CP_WAIT1();
        } else {
            CP_WAIT0();
        }
        __syncthreads();

        uint32_t ah_u = (uint32_t)__cvta_generic_to_shared(pAH[cur]);
        uint32_t al_u = (uint32_t)__cvta_generic_to_shared(pAL[cur]);
        uint32_t bh_u = (uint32_t)__cvta_generic_to_shared(pBH[cur]);
        uint32_t bl_u = (uint32_t)__cvta_generic_to_shared(pBL[cur]);

        #pragma unroll
        for (int kk = 0; kk < 32; kk += 16) {
            uint32_t ah[4][4], al[4][4], bh[4][2], bl[4][2];
            int arow = wm + (lane & 7) + ((lane >> 3) & 1) * 8;
            int acol = kk + (lane >> 4) * 8;
            #pragma unroll
            for (int mi = 0; mi < 4; mi++) {
                uint32_t ad = ah_u + (uint32_t)(((arow + mi*16)*ASTR + acol) * 2);
                ldsm_x4(ah[mi][0], ah[mi][1], ah[mi][2], ah[mi][3], ad);
                ad = al_u + (uint32_t)(((arow + mi*16)*ASTR + acol) * 2);
                ldsm_x4(al[mi][0], al[mi][1], al[mi][2], al[mi][3], ad);
            }
            int brow = kk + (lane & 15);
            #pragma unroll
            for (int ni = 0; ni < 4; ni++) {
                uint32_t bd = bh_u + (uint32_t)((brow*BSTR + wn + ni*8) * 2);
                ldsm_x2t(bh[ni][0], bh[ni][1], bd);
                bd = bl_u + (uint32_t)((brow*BSTR + wn + ni*8) * 2);
                ldsm_x2t(bl[ni][0], bl[ni][1], bd);
            }
            #pragma unroll
            for (int mi = 0; mi < 4; mi++)
                #pragma unroll
                for (int ni = 0; ni < 4; ni++) {
                    mma_bf16(acc[mi][ni], ah[mi], bh[ni]);
                    mma_bf16(acc[mi][ni], ah[mi], bl[ni]);
                    mma_bf16(acc[mi][ni], al[mi], bh[ni]);
                }
        }
        __syncthreads();
    }

    #pragma unroll
    for (int mi = 0; mi < 4; mi++) {
        int m = bm*128 + wm + mi*16 + (lane >> 2);
        float bi0 = bias[m], bi8 = bias[m + 8];
        #pragma unroll
        for (int ni = 0; ni < 4; ni++) {
            int n = bn*128 + wn + ni*8 + (lane & 3)*2;
            float2 v0 = make_float2(acc[mi][ni][0] + bi0, acc[mi][ni][1] + bi0);
            float2 v1 = make_float2(acc[mi][ni][2] + bi8, acc[mi][ni][3] + bi8);
            *(float2*)(out + (size_t)(bz*HN + m)*LN + n)     = v0;
            *(float2*)(out + (size_t)(bz*HN + m + 8)*LN + n) = v1;
        }
    }
}

// ---------------- launch ----------------
extern "C" void kernel_launch(void* const* d_in, const int* in_sizes, int n_in,
                              void* d_out, int out_size)
{
    const float* u     = (const float*)d_in[0];
    const float* a     = (const float*)d_in[1];
    const float* theta = (const float*)d_in[2];
    const float* bcoef = (const float*)d_in[3];
    const float* ccoef = (const float*)d_in[4];
    const float* x0    = (const float*)d_in[5];
    const float* Dv    = (const float*)d_in[6];
    const float* W     = (const float*)d_in[7];
    const float* bias  = (const float*)d_in[8];
    float* out = (float*)d_out;

    const int gemm_smem = (4*A_ST + 4*B_ST) * 2;   // 75776 bytes
    static cudaStream_t s2 = nullptr;
    static cudaEvent_t evFork = nullptr, evJoin = nullptr;
    if (!s2) {   // one-time setup on the (non-captured) correctness call
        cudaFuncSetAttribute(k_gemm_tc, cudaFuncAttributeMaxDynamicSharedMemorySize, gemm_smem);
        cudaStreamCreateWithFlags(&s2, cudaStreamNonBlocking);
        cudaEventCreateWithFlags(&evFork, cudaEventDisableTiming);
        cudaEventCreateWithFlags(&evJoin, cudaEventDisableTiming);
    }

    // fork: k_tables (f/k0) runs concurrently with k_tables2 on the main stream.
    cudaEventRecord(evFork, 0);
    cudaStreamWaitEvent(s2, evFork, 0);
    k_tables <<<HN, 128, 0, s2>>>(a, theta, bcoef, ccoef, x0);
    cudaEventRecord(evJoin, s2);

    k_tables2<<<8192 + HN*HN/256, 256>>>(a, theta, bcoef, ccoef, W);

    cudaStreamWaitEvent(0, evJoin, 0);   // join before k_main consumes g_f/g_k0
    k_main   <<<BSZ*HN, 256>>>(u, Dv);
    k_gemm_tc<<<dim3(LN/128, HN/128, BSZ), 256, gemm_smem>>>(bias, out);
}